// round 16
// baseline (speedup 1.0000x reference)
#include <cuda_runtime.h>
#include <cuda_fp16.h>
#include <cstdint>

#define Sq   2048
#define DKd  64
#define TQt  128
#define TKt  128
#define NTHR 512
#define NBH  64
#define NKT  (Sq / TKt)   // 16

#define SB   144    // fp16 tile row stride bytes (72 fp16)
#define SPB  272    // P row stride bytes (136 fp16)
#define TILEB (TKt * DKd * 2)
#define BHB   (Sq * DKd * 2)

// smem layout: P0 aliases Q region; REDC/INV alias P1 head
#define OFF_Q    0
#define OFF_P0   0
#define OFF_P1   34816
#define OFF_REDC 34816
#define OFF_INV  36864
#define OFF_K0   69632
#define OFF_K1   88064
#define OFF_V0   106496
#define OFF_V1   124928
#define OFF_V2   143360
#define SMEM_BYTES 161792

#define TOTW (NBH * Sq * DKd / 2)
__device__ uint32_t Q16g[TOTW];
__device__ uint32_t K16g[TOTW];
__device__ uint32_t V16g[TOTW];

#define MMAH(c, a, b) \
    asm volatile("mma.sync.aligned.m16n8k16.row.col.f32.f16.f16.f32 " \
        "{%0,%1,%2,%3}, {%4,%5,%6,%7}, {%8,%9}, {%0,%1,%2,%3};" \
        : "+f"((c)[0]), "+f"((c)[1]), "+f"((c)[2]), "+f"((c)[3]) \
        : "r"((a)[0]), "r"((a)[1]), "r"((a)[2]), "r"((a)[3]), \
          "r"((b)[0]), "r"((b)[1]))

__device__ __forceinline__ uint32_t smem_u32(const void* p) {
    uint32_t a;
    asm("{ .reg .u64 t; cvta.to.shared.u64 t, %1; cvt.u32.u64 %0, t; }" : "=r"(a) : "l"(p));
    return a;
}
__device__ __forceinline__ void ldm4(uint32_t r[4], uint32_t addr) {
    asm volatile("ldmatrix.sync.aligned.m8n8.x4.shared.b16 {%0,%1,%2,%3}, [%4];"
                 : "=r"(r[0]), "=r"(r[1]), "=r"(r[2]), "=r"(r[3]) : "r"(addr));
}
__device__ __forceinline__ void ldm2t(uint32_t& r0, uint32_t& r1, uint32_t addr) {
    asm volatile("ldmatrix.sync.aligned.m8n8.x2.trans.shared.b16 {%0,%1}, [%2];"
                 : "=r"(r0), "=r"(r1) : "r"(addr));
}
__device__ __forceinline__ uint32_t packh(float a, float b) {
    __half2 h = __floats2half2_rn(a, b);
    return *(uint32_t*)&h;
}
__device__ __forceinline__ void cpa16(uint32_t dst, const void* src) {
    asm volatile("cp.async.cg.shared.global [%0], [%1], 16;" :: "r"(dst), "l"(src));
}
#define CP_COMMIT() asm volatile("cp.async.commit_group;" ::: "memory")
#define CP_WAIT0()  asm volatile("cp.async.wait_group 0;" ::: "memory")

__device__ __forceinline__ void cp_tile(uint32_t smdst, const char* gsrc, int t) {
    #pragma unroll
    for (int i = 0; i < 2; i++) {
        int c = t + i * NTHR;
        int row = c >> 3, col = (c & 7) * 16;
        cpa16(smdst + row * SB + col, gsrc + row * 128 + col);
    }
}

__global__ void cvt_kernel(const float4* __restrict__ Q,
                           const float4* __restrict__ K,
                           const float4* __restrict__ V)
{
    int i = blockIdx.x * blockDim.x + threadIdx.x;
    if (i < TOTW / 2) {
        float4 q = Q[i];
        ((uint2*)Q16g)[i] = make_uint2(packh(q.x, q.y), packh(q.z, q.w));
        float4 k = K[i];
        ((uint2*)K16g)[i] = make_uint2(packh(k.x, k.y), packh(k.z, k.w));
        float4 v = V[i];
        ((uint2*)V16g)[i] = make_uint2(packh(v.x, v.y), packh(v.z, v.w));
    }
}

__global__ __launch_bounds__(NTHR, 1)
void sdpa_mma_kernel(float* __restrict__ out_ctx,
                     float* __restrict__ out_attn)
{
    extern __shared__ char smc[];
    const uint32_t smb = smem_u32(smc);
    const int t    = threadIdx.x;
    const int wid  = t >> 5;
    const int lane = t & 31;
    const int g    = lane >> 2;
    const int tg   = lane & 3;
    const int mw   = wid >> 2;
    const int nw   = wid & 3;
    const int bh   = blockIdx.y;
    const int qt   = (NKT - 1) - blockIdx.x;   // heavy tiles launch first
    const int q0   = qt * TQt;

    const int aRow = (lane & 7) + ((lane >> 3) & 1) * 8;
    const int aCol = (lane >> 4) * 8;
    const int bRow = (lane & 7) + (lane >> 4) * 8;
    const int bCol = ((lane >> 3) & 1) * 8;
    const int vRow = lane & 15;

    const int KOFF[2] = { OFF_K0, OFF_K1 };
    const int VOFF[3] = { OFF_V0, OFF_V1, OFF_V2 };
    const int PB[2]   = { OFF_P0, OFF_P1 };

    const char* Qh = (const char*)Q16g + (size_t)bh * BHB;
    const char* Kh = (const char*)K16g + (size_t)bh * BHB;
    const char* Vh = (const char*)V16g + (size_t)bh * BHB;
    float* attn_q = out_attn + ((size_t)bh * Sq + q0) * Sq;

    // prologue: Q tile + K0 via cp.async
    cp_tile(smb + OFF_Q, Qh + (size_t)q0 * DKd * 2, t);
    cp_tile(smb + OFF_K0, Kh, t);
    CP_COMMIT();

    // zero-fill attn above the causal tiles (overlaps the copies)
    {
        int zc0 = (qt + 1) * TKt;
        int zf4 = (Sq - zc0) >> 2;
        if (zf4 > 0) {
            float4 z = make_float4(0.f, 0.f, 0.f, 0.f);
            for (int idx = t; idx < TQt * zf4; idx += NTHR) {
                int rr = idx / zf4, c4 = idx - rr * zf4;
                *(float4*)(attn_q + (size_t)rr * Sq + zc0 + c4 * 4) = z;
            }
        }
    }
    CP_WAIT0();
    __syncthreads();

    // Q-hi fragments register-resident for the whole kernel
    uint32_t qhr[4][2][4];
    #pragma unroll
    for (int ks = 0; ks < 4; ks++)
        #pragma unroll
        for (int mi = 0; mi < 2; mi++) {
            int r0 = mw * 32 + mi * 16 + aRow;
            ldm4(qhr[ks][mi], smb + OFF_Q + r0 * SB + (ks * 16 + aCol) * 2);
        }

    float sc[2][2] = {{0.f, 0.f}, {0.f, 0.f}};

    // ====== PASS 1: denominators (causal tiles, 1-term QK, cp.async K) ======
    for (int kt = 0; kt <= qt; kt++) {
        const int buf = kt & 1;

        if (kt < qt) {
            cp_tile(smb + KOFF[1 - buf], Kh + (size_t)(kt + 1) * TILEB, t);
            CP_COMMIT();
        }

        float c[2][4][4];
        #pragma unroll
        for (int mi = 0; mi < 2; mi++)
            #pragma unroll
            for (int ni = 0; ni < 4; ni++)
                #pragma unroll
                for (int e = 0; e < 4; e++) c[mi][ni][e] = 0.f;

        #pragma unroll
        for (int ks = 0; ks < 4; ks++) {
            int kc = ks * 16;
            uint32_t bhf[2][4];
            #pragma unroll
            for (int p = 0; p < 2; p++) {
                int n0 = nw * 32 + p * 16 + bRow;
                ldm4(bhf[p], smb + KOFF[buf] + n0 * SB + (kc + bCol) * 2);
            }
            #pragma unroll
            for (int mi = 0; mi < 2; mi++)
                #pragma unroll
                for (int ni = 0; ni < 4; ni++) {
                    const uint32_t* bb = &bhf[ni >> 1][(ni & 1) * 2];
                    MMAH(c[mi][ni], qhr[ks][mi], bb);
                }
        }

        #pragma unroll
        for (int mi = 0; mi < 2; mi++) {
            int rg = q0 + mw * 32 + mi * 16 + g;
            #pragma unroll
            for (int ni = 0; ni < 4; ni++) {
                int cl = kt * TKt + nw * 32 + ni * 8 + 2 * tg;
                float e0 = __expf(c[mi][ni][0] * 0.125f);
                float e1 = __expf(c[mi][ni][1] * 0.125f);
                float e2 = __expf(c[mi][ni][2] * 0.125f);
                float e3 = __expf(c[mi][ni][3] * 0.125f);
                if (kt < qt) {
                    sc[mi][0] += e0 + e1;
                    sc[mi][1] += e2 + e3;
                } else {
                    if (cl     <= rg) sc[mi][0] += e0;
                    if (cl + 1 <= rg) sc[mi][0] += e1;
                    if (cl     <= rg + 8) sc[mi][1] += e2;
                    if (cl + 1 <= rg + 8) sc[mi][1] += e3;
                }
            }
        }

        CP_WAIT0();
        __syncthreads();
    }

    // ---- reduce denominators ----
    {
        float* redc = (float*)(smc + OFF_REDC);
        #pragma unroll
        for (int mi = 0; mi < 2; mi++)
            #pragma unroll
            for (int rr = 0; rr < 2; rr++) {
                float vc = sc[mi][rr];
                vc += __shfl_xor_sync(0xffffffffu, vc, 1);
                vc += __shfl_xor_sync(0xffffffffu, vc, 2);
                if (tg == 0) {
                    int row = mw * 32 + mi * 16 + rr * 8 + g;
                    redc[row * 4 + nw] = vc;
                }
            }
    }
    // pass-2 prologue copies overlap the reduction
    cp_tile(smb + OFF_K0, Kh, t);
    cp_tile(smb + OFF_V0, Vh, t);
    CP_COMMIT();
    __syncthreads();
    if (t < TQt) {
        const float* rc = (const float*)(smc + OFF_REDC) + t * 4;
        float vc = (rc[0] + rc[1]) + (rc[2] + rc[3]);
        ((float*)(smc + OFF_INV))[t] = 1.0f / vc;
    }
    CP_WAIT0();
    __syncthreads();

    float invr[2][2];
    #pragma unroll
    for (int mi = 0; mi < 2; mi++) {
        invr[mi][0] = ((const float*)(smc + OFF_INV))[mw * 32 + mi * 16 + g];
        invr[mi][1] = ((const float*)(smc + OFF_INV))[mw * 32 + mi * 16 + g + 8];
    }

    // ============ PASS 2: attn + context (1 sync/tile) ============
    float av[2][2][4];
    #pragma unroll
    for (int mi = 0; mi < 2; mi++)
        #pragma unroll
        for (int ni = 0; ni < 2; ni++)
            #pragma unroll
            for (int e = 0; e < 4; e++) av[mi][ni][e] = 0.f;

    for (int kt = 0; kt <= qt; kt++) {
        const int buf = kt & 1;
        const bool diag = (kt == qt);

        if (kt < qt) {
            cp_tile(smb + KOFF[1 - buf], Kh + (size_t)(kt + 1) * TILEB, t);
            cp_tile(smb + VOFF[(kt + 1) % 3], Vh + (size_t)(kt + 1) * TILEB, t);
            CP_COMMIT();
        }

        // QK 1-term: qhr x Khi[buf]
        float c[2][4][4];
        #pragma unroll
        for (int mi = 0; mi < 2; mi++)
            #pragma unroll
            for (int ni = 0; ni < 4; ni++)
                #pragma unroll
                for (int e = 0; e < 4; e++) c[mi][ni][e] = 0.f;

        #pragma unroll
        for (int ks = 0; ks < 4; ks++) {
            int kc = ks * 16;
            uint32_t bhf[2][4];
            #pragma unroll
            for (int p = 0; p < 2; p++) {
                int n0 = nw * 32 + p * 16 + bRow;
                ldm4(bhf[p], smb + KOFF[buf] + n0 * SB + (kc + bCol) * 2);
            }
            #pragma unroll
            for (int mi = 0; mi < 2; mi++)
                #pragma unroll
                for (int ni = 0; ni < 4; ni++) {
                    const uint32_t* bb = &bhf[ni >> 1][(ni & 1) * 2];
                    MMAH(c[mi][ni], qhr[ks][mi], bb);
                }
        }

        // P = exp*inv (masked on diag) -> fp16 smem [buf]
        #pragma unroll
        for (int mi = 0; mi < 2; mi++) {
            int rloc0 = mw * 32 + mi * 16 + g;
            int rg = q0 + rloc0;
            #pragma unroll
            for (int ni = 0; ni < 4; ni++) {
                int cl = nw * 32 + ni * 8 + 2 * tg;
                int cg = kt * TKt + cl;
                float p0 = __expf(c[mi][ni][0] * 0.125f) * invr[mi][0];
                float p1 = __expf(c[mi][ni][1] * 0.125f) * invr[mi][0];
                float p2 = __expf(c[mi][ni][2] * 0.125f) * invr[mi][1];
                float p3 = __expf(c[mi][ni][3] * 0.125f) * invr[mi][1];
                if (diag) {
                    p0 = (cg     <= rg) ? p0 : 0.f;
                    p1 = (cg + 1 <= rg) ? p1 : 0.f;
                    p2 = (cg     <= rg + 8) ? p2 : 0.f;
                    p3 = (cg + 1 <= rg + 8) ? p3 : 0.f;
                }
                *(uint32_t*)(smc + PB[buf] + rloc0 * SPB + cl * 2)       = packh(p0, p1);
                *(uint32_t*)(smc + PB[buf] + (rloc0 + 8) * SPB + cl * 2) = packh(p2, p3);
            }
        }
        CP_WAIT0();
        __syncthreads();   // the single per-tile barrier

        // context += P @ Vhi FIRST (critical path; P already normalized)
        #pragma unroll
        for (int ks = 0; ks < 8; ks++) {
            int kc = ks * 16;
            uint32_t ap[2][4];
            #pragma unroll
            for (int mi = 0; mi < 2; mi++) {
                int r0 = mw * 32 + mi * 16 + aRow;
                ldm4(ap[mi], smb + PB[buf] + r0 * SPB + (kc + aCol) * 2);
            }
            #pragma unroll
            for (int ni = 0; ni < 2; ni++) {
                int dv0 = nw * 16 + ni * 8;
                uint32_t bhv[2];
                ldm2t(bhv[0], bhv[1], smb + VOFF[kt % 3] + (kc + vRow) * SB + dv0 * 2);
                #pragma unroll
                for (int mi = 0; mi < 2; mi++)
                    MMAH(av[mi][ni], ap[mi], bhv);
            }
        }

        // coalesced attn write AFTER PV (off the critical path; P[buf] is
        // only rewritten at kt+2, behind the barrier inside kt+1)
        {
            float* abase = attn_q + kt * TKt;
            #pragma unroll
            for (int r = 0; r < 8; r++) {
                int row = wid * 8 + r;
                uint2 pv = *(const uint2*)(smc + PB[buf] + row * SPB + lane * 8);
                float2 f0 = __half22float2(*(__half2*)&pv.x);
                float2 f1 = __half22float2(*(__half2*)&pv.y);
                *(float4*)(abase + (size_t)row * Sq + lane * 4) =
                    make_float4(f0.x, f0.y, f1.x, f1.y);
            }
        }
    }

    // ---- context output ----
    #pragma unroll
    for (int mi = 0; mi < 2; mi++) {
        int rloc0 = mw * 32 + mi * 16 + g;
        #pragma unroll
        for (int ni = 0; ni < 2; ni++) {
            int cl = nw * 16 + ni * 8 + 2 * tg;
            *(float2*)(out_ctx + ((size_t)bh * Sq + q0 + rloc0) * DKd + cl) =
                make_float2(av[mi][ni][0], av[mi][ni][1]);
            *(float2*)(out_ctx + ((size_t)bh * Sq + q0 + rloc0 + 8) * DKd + cl) =
                make_float2(av[mi][ni][2], av[mi][ni][3]);
        }
    }
}

extern "C" void kernel_launch(void* const* d_in, const int* in_sizes, int n_in,
                              void* d_out, int out_size)
{
    const float* Q = (const float*)d_in[0];
    const float* K = (const float*)d_in[1];
    const float* V = (const float*)d_in[2];
    float* ctx  = (float*)d_out;
    float* attn = (float*)d_out + (size_t)NBH * Sq * DKd;

    int nf4 = TOTW / 2;
    cvt_kernel<<<(nf4 + 255) / 256, 256>>>((const float4*)Q, (const float4*)K, (const float4*)V);

    cudaFuncSetAttribute(sdpa_mma_kernel, cudaFuncAttributeMaxDynamicSharedMemorySize, SMEM_BYTES);
    dim3 grid(Sq / TQt, NBH);
    sdpa_mma_kernel<<<grid, NTHR, SMEM_BYTES>>>(ctx, attn);
    (void)in_sizes; (void)n_in; (void)out_size;
}

// round 17
// speedup vs baseline: 1.1260x; 1.1260x over previous
#include <cuda_runtime.h>
#include <cuda_fp16.h>
#include <cstdint>

#define Sq   2048
#define DKd  64
#define TQt  128
#define TKt  128
#define NTHR 512
#define NBH  64
#define NKT  (Sq / TKt)   // 16

#define SB   144    // fp16 tile row stride bytes (72 fp16)
#define SPB  272    // P row stride bytes (136 fp16)
#define TILEB (TKt * DKd * 2)
#define BHB   (Sq * DKd * 2)
#define E2S  0.18033688011112042f   // 0.125 * log2(e)

// smem layout: P0 aliases Q region; REDC/INV alias P1 head
#define OFF_Q    0
#define OFF_P0   0
#define OFF_P1   34816
#define OFF_REDC 34816
#define OFF_INV  36864
#define OFF_K0   69632
#define OFF_K1   88064
#define OFF_V0   106496
#define OFF_V1   124928
#define OFF_V2   143360
#define SMEM_BYTES 161792

#define TOTW (NBH * Sq * DKd / 2)
__device__ uint32_t Q16g[TOTW];
__device__ uint32_t K16g[TOTW];
__device__ uint32_t V16g[TOTW];

#define MMAH(c, a, b) \
    asm volatile("mma.sync.aligned.m16n8k16.row.col.f32.f16.f16.f32 " \
        "{%0,%1,%2,%3}, {%4,%5,%6,%7}, {%8,%9}, {%0,%1,%2,%3};" \
        : "+f"((c)[0]), "+f"((c)[1]), "+f"((c)[2]), "+f"((c)[3]) \
        : "r"((a)[0]), "r"((a)[1]), "r"((a)[2]), "r"((a)[3]), \
          "r"((b)[0]), "r"((b)[1]))

__device__ __forceinline__ uint32_t smem_u32(const void* p) {
    uint32_t a;
    asm("{ .reg .u64 t; cvta.to.shared.u64 t, %1; cvt.u32.u64 %0, t; }" : "=r"(a) : "l"(p));
    return a;
}
__device__ __forceinline__ void ldm4(uint32_t r[4], uint32_t addr) {
    asm volatile("ldmatrix.sync.aligned.m8n8.x4.shared.b16 {%0,%1,%2,%3}, [%4];"
                 : "=r"(r[0]), "=r"(r[1]), "=r"(r[2]), "=r"(r[3]) : "r"(addr));
}
__device__ __forceinline__ void ldm2t(uint32_t& r0, uint32_t& r1, uint32_t addr) {
    asm volatile("ldmatrix.sync.aligned.m8n8.x2.trans.shared.b16 {%0,%1}, [%2];"
                 : "=r"(r0), "=r"(r1) : "r"(addr));
}
__device__ __forceinline__ uint32_t packh(float a, float b) {
    __half2 h = __floats2half2_rn(a, b);
    return *(uint32_t*)&h;
}
__device__ __forceinline__ void cpa16(uint32_t dst, const void* src) {
    asm volatile("cp.async.cg.shared.global [%0], [%1], 16;" :: "r"(dst), "l"(src));
}
#define CP_COMMIT() asm volatile("cp.async.commit_group;" ::: "memory")
#define CP_WAIT0()  asm volatile("cp.async.wait_group 0;" ::: "memory")

__device__ __forceinline__ void cp_tile(uint32_t smdst, const char* gsrc, int t) {
    #pragma unroll
    for (int i = 0; i < 2; i++) {
        int c = t + i * NTHR;
        int row = c >> 3, col = (c & 7) * 16;
        cpa16(smdst + row * SB + col, gsrc + row * 128 + col);
    }
}

__global__ void cvt_kernel(const float4* __restrict__ Q,
                           const float4* __restrict__ K,
                           const float4* __restrict__ V)
{
    int i = blockIdx.x * blockDim.x + threadIdx.x;
    if (i < TOTW / 2) {
        float4 q = Q[i];
        ((uint2*)Q16g)[i] = make_uint2(packh(q.x, q.y), packh(q.z, q.w));
        float4 k = K[i];
        ((uint2*)K16g)[i] = make_uint2(packh(k.x, k.y), packh(k.z, k.w));
        float4 v = V[i];
        ((uint2*)V16g)[i] = make_uint2(packh(v.x, v.y), packh(v.z, v.w));
    }
}

__global__ __launch_bounds__(NTHR, 1)
void sdpa_mma_kernel(float* __restrict__ out_ctx,
                     float* __restrict__ out_attn)
{
    extern __shared__ char smc[];
    const uint32_t smb = smem_u32(smc);
    const int t    = threadIdx.x;
    const int wid  = t >> 5;
    const int lane = t & 31;
    const int g    = lane >> 2;
    const int tg   = lane & 3;
    const int mw   = wid >> 2;
    const int nw   = wid & 3;
    const int bh   = blockIdx.y;
    const int qt   = (NKT - 1) - blockIdx.x;   // heavy tiles launch first
    const int q0   = qt * TQt;

    const int aRow = (lane & 7) + ((lane >> 3) & 1) * 8;
    const int aCol = (lane >> 4) * 8;
    const int bRow = (lane & 7) + (lane >> 4) * 8;
    const int bCol = ((lane >> 3) & 1) * 8;
    const int vRow = lane & 15;

    // pass 1 uses 4 K buffers (V region is free then); pass 2 uses 2
    const int K4[4]   = { OFF_K0, OFF_K1, OFF_V0, OFF_V1 };
    const int KOFF[2] = { OFF_K0, OFF_K1 };
    const int VOFF[3] = { OFF_V0, OFF_V1, OFF_V2 };
    const int PB[2]   = { OFF_P0, OFF_P1 };

    const char* Qh = (const char*)Q16g + (size_t)bh * BHB;
    const char* Kh = (const char*)K16g + (size_t)bh * BHB;
    const char* Vh = (const char*)V16g + (size_t)bh * BHB;
    float* attn_q = out_attn + ((size_t)bh * Sq + q0) * Sq;

    // prologue: Q tile + K tiles 0,1 via cp.async
    cp_tile(smb + OFF_Q, Qh + (size_t)q0 * DKd * 2, t);
    cp_tile(smb + K4[0], Kh, t);
    if (qt >= 1) cp_tile(smb + K4[1], Kh + TILEB, t);
    CP_COMMIT();

    // zero-fill attn above the causal tiles (overlaps the copies)
    {
        int zc0 = (qt + 1) * TKt;
        int zf4 = (Sq - zc0) >> 2;
        if (zf4 > 0) {
            float4 z = make_float4(0.f, 0.f, 0.f, 0.f);
            for (int idx = t; idx < TQt * zf4; idx += NTHR) {
                int rr = idx / zf4, c4 = idx - rr * zf4;
                *(float4*)(attn_q + (size_t)rr * Sq + zc0 + c4 * 4) = z;
            }
        }
    }
    CP_WAIT0();
    __syncthreads();

    // Q-hi fragments register-resident for the whole kernel
    uint32_t qhr[4][2][4];
    #pragma unroll
    for (int ks = 0; ks < 4; ks++)
        #pragma unroll
        for (int mi = 0; mi < 2; mi++) {
            int r0 = mw * 32 + mi * 16 + aRow;
            ldm4(qhr[ks][mi], smb + OFF_Q + r0 * SB + (ks * 16 + aCol) * 2);
        }

    float sc[2][2] = {{0.f, 0.f}, {0.f, 0.f}};

    // ====== PASS 1: denominators — TWO k-tiles per barrier interval ======
    for (int kp = 0; kp <= qt; kp += 2) {
        // prefetch the next pair
        if (kp + 2 <= qt) {
            cp_tile(smb + K4[(kp + 2) & 3], Kh + (size_t)(kp + 2) * TILEB, t);
            if (kp + 3 <= qt)
                cp_tile(smb + K4[(kp + 3) & 3], Kh + (size_t)(kp + 3) * TILEB, t);
            CP_COMMIT();
        }

        #pragma unroll
        for (int sub = 0; sub < 2; sub++) {
            const int kt = kp + sub;
            if (kt > qt) break;

            float c[2][4][4];
            #pragma unroll
            for (int mi = 0; mi < 2; mi++)
                #pragma unroll
                for (int ni = 0; ni < 4; ni++)
                    #pragma unroll
                    for (int e = 0; e < 4; e++) c[mi][ni][e] = 0.f;

            #pragma unroll
            for (int ks = 0; ks < 4; ks++) {
                int kc = ks * 16;
                uint32_t bhf[2][4];
                #pragma unroll
                for (int p = 0; p < 2; p++) {
                    int n0 = nw * 32 + p * 16 + bRow;
                    ldm4(bhf[p], smb + K4[kt & 3] + n0 * SB + (kc + bCol) * 2);
                }
                #pragma unroll
                for (int mi = 0; mi < 2; mi++)
                    #pragma unroll
                    for (int ni = 0; ni < 4; ni++) {
                        const uint32_t* bb = &bhf[ni >> 1][(ni & 1) * 2];
                        MMAH(c[mi][ni], qhr[ks][mi], bb);
                    }
            }

            #pragma unroll
            for (int mi = 0; mi < 2; mi++) {
                int rg = q0 + mw * 32 + mi * 16 + g;
                #pragma unroll
                for (int ni = 0; ni < 4; ni++) {
                    int cl = kt * TKt + nw * 32 + ni * 8 + 2 * tg;
                    float e0 = exp2f(c[mi][ni][0] * E2S);
                    float e1 = exp2f(c[mi][ni][1] * E2S);
                    float e2 = exp2f(c[mi][ni][2] * E2S);
                    float e3 = exp2f(c[mi][ni][3] * E2S);
                    if (kt < qt) {
                        sc[mi][0] += e0 + e1;
                        sc[mi][1] += e2 + e3;
                    } else {
                        if (cl     <= rg) sc[mi][0] += e0;
                        if (cl + 1 <= rg) sc[mi][0] += e1;
                        if (cl     <= rg + 8) sc[mi][1] += e2;
                        if (cl + 1 <= rg + 8) sc[mi][1] += e3;
                    }
                }
            }
        }

        CP_WAIT0();
        __syncthreads();
    }

    // ---- reduce denominators ----
    {
        float* redc = (float*)(smc + OFF_REDC);
        #pragma unroll
        for (int mi = 0; mi < 2; mi++)
            #pragma unroll
            for (int rr = 0; rr < 2; rr++) {
                float vc = sc[mi][rr];
                vc += __shfl_xor_sync(0xffffffffu, vc, 1);
                vc += __shfl_xor_sync(0xffffffffu, vc, 2);
                if (tg == 0) {
                    int row = mw * 32 + mi * 16 + rr * 8 + g;
                    redc[row * 4 + nw] = vc;
                }
            }
    }
    // pass-2 prologue copies overlap the reduction
    cp_tile(smb + OFF_K0, Kh, t);
    cp_tile(smb + OFF_V0, Vh, t);
    CP_COMMIT();
    __syncthreads();
    if (t < TQt) {
        const float* rc = (const float*)(smc + OFF_REDC) + t * 4;
        float vc = (rc[0] + rc[1]) + (rc[2] + rc[3]);
        ((float*)(smc + OFF_INV))[t] = 1.0f / vc;
    }
    CP_WAIT0();
    __syncthreads();

    float invr[2][2];
    #pragma unroll
    for (int mi = 0; mi < 2; mi++) {
        invr[mi][0] = ((const float*)(smc + OFF_INV))[mw * 32 + mi * 16 + g];
        invr[mi][1] = ((const float*)(smc + OFF_INV))[mw * 32 + mi * 16 + g + 8];
    }

    // ============ PASS 2: attn + context (R14 structure, 1 sync/tile) ============
    float av[2][2][4];
    #pragma unroll
    for (int mi = 0; mi < 2; mi++)
        #pragma unroll
        for (int ni = 0; ni < 2; ni++)
            #pragma unroll
            for (int e = 0; e < 4; e++) av[mi][ni][e] = 0.f;

    for (int kt = 0; kt <= qt; kt++) {
        const int buf = kt & 1;
        const bool diag = (kt == qt);

        if (kt < qt) {
            cp_tile(smb + KOFF[1 - buf], Kh + (size_t)(kt + 1) * TILEB, t);
            cp_tile(smb + VOFF[(kt + 1) % 3], Vh + (size_t)(kt + 1) * TILEB, t);
            CP_COMMIT();
        }

        // QK 1-term: qhr x Khi[buf]
        float c[2][4][4];
        #pragma unroll
        for (int mi = 0; mi < 2; mi++)
            #pragma unroll
            for (int ni = 0; ni < 4; ni++)
                #pragma unroll
                for (int e = 0; e < 4; e++) c[mi][ni][e] = 0.f;

        #pragma unroll
        for (int ks = 0; ks < 4; ks++) {
            int kc = ks * 16;
            uint32_t bhf[2][4];
            #pragma unroll
            for (int p = 0; p < 2; p++) {
                int n0 = nw * 32 + p * 16 + bRow;
                ldm4(bhf[p], smb + KOFF[buf] + n0 * SB + (kc + bCol) * 2);
            }
            #pragma unroll
            for (int mi = 0; mi < 2; mi++)
                #pragma unroll
                for (int ni = 0; ni < 4; ni++) {
                    const uint32_t* bb = &bhf[ni >> 1][(ni & 1) * 2];
                    MMAH(c[mi][ni], qhr[ks][mi], bb);
                }
        }

        // P = exp*inv (masked on diag): attn gmem fp32 (scattered, overlapped)
        // + P fp16 smem [buf]  — exact R14 epilogue (best measured)
        #pragma unroll
        for (int mi = 0; mi < 2; mi++) {
            int rloc0 = mw * 32 + mi * 16 + g;
            int rg = q0 + rloc0;
            #pragma unroll
            for (int ni = 0; ni < 4; ni++) {
                int cl = nw * 32 + ni * 8 + 2 * tg;
                int cg = kt * TKt + cl;
                float p0 = exp2f(c[mi][ni][0] * E2S) * invr[mi][0];
                float p1 = exp2f(c[mi][ni][1] * E2S) * invr[mi][0];
                float p2 = exp2f(c[mi][ni][2] * E2S) * invr[mi][1];
                float p3 = exp2f(c[mi][ni][3] * E2S) * invr[mi][1];
                if (diag) {
                    p0 = (cg     <= rg) ? p0 : 0.f;
                    p1 = (cg + 1 <= rg) ? p1 : 0.f;
                    p2 = (cg     <= rg + 8) ? p2 : 0.f;
                    p3 = (cg + 1 <= rg + 8) ? p3 : 0.f;
                }
                *(float2*)(attn_q + (size_t)rloc0 * Sq + cg)       = make_float2(p0, p1);
                *(float2*)(attn_q + (size_t)(rloc0 + 8) * Sq + cg) = make_float2(p2, p3);
                *(uint32_t*)(smc + PB[buf] + rloc0 * SPB + cl * 2)       = packh(p0, p1);
                *(uint32_t*)(smc + PB[buf] + (rloc0 + 8) * SPB + cl * 2) = packh(p2, p3);
            }
        }
        CP_WAIT0();
        __syncthreads();   // the single per-tile barrier

        // context += P @ Vhi (P already normalized)
        #pragma unroll
        for (int ks = 0; ks < 8; ks++) {
            int kc = ks * 16;
            uint32_t ap[2][4];
            #pragma unroll
            for (int mi = 0; mi < 2; mi++) {
                int r0 = mw * 32 + mi * 16 + aRow;
                ldm4(ap[mi], smb + PB[buf] + r0 * SPB + (kc + aCol) * 2);
            }
            #pragma unroll
            for (int ni = 0; ni < 2; ni++) {
                int dv0 = nw * 16 + ni * 8;
                uint32_t bhv[2];
                ldm2t(bhv[0], bhv[1], smb + VOFF[kt % 3] + (kc + vRow) * SB + dv0 * 2);
                #pragma unroll
                for (int mi = 0; mi < 2; mi++)
                    MMAH(av[mi][ni], ap[mi], bhv);
            }
        }
    }

    // ---- context output ----
    #pragma unroll
    for (int mi = 0; mi < 2; mi++) {
        int rloc0 = mw * 32 + mi * 16 + g;
        #pragma unroll
        for (int ni = 0; ni < 2; ni++) {
            int cl = nw * 16 + ni * 8 + 2 * tg;
            *(float2*)(out_ctx + ((size_t)bh * Sq + q0 + rloc0) * DKd + cl) =
                make_float2(av[mi][ni][0], av[mi][ni][1]);
            *(float2*)(out_ctx + ((size_t)bh * Sq + q0 + rloc0 + 8) * DKd + cl) =
                make_float2(av[mi][ni][2], av[mi][ni][3]);
        }
    }
}

extern "C" void kernel_launch(void* const* d_in, const int* in_sizes, int n_in,
                              void* d_out, int out_size)
{
    const float* Q = (const float*)d_in[0];
    const float* K = (const float*)d_in[1];
    const float* V = (const float*)d_in[2];
    float* ctx  = (float*)d_out;
    float* attn = (float*)d_out + (size_t)NBH * Sq * DKd;

    int nf4 = TOTW / 2;
    cvt_kernel<<<(nf4 + 255) / 256, 256>>>((const float4*)Q, (const float4*)K, (const float4*)V);

    cudaFuncSetAttribute(sdpa_mma_kernel, cudaFuncAttributeMaxDynamicSharedMemorySize, SMEM_BYTES);
    dim3 grid(Sq / TQt, NBH);
    sdpa_mma_kernel<<<grid, NTHR, SMEM_BYTES>>>(ctx, attn);
    (void)in_sizes; (void)n_in; (void)out_size;
}